// round 2
// baseline (speedup 1.0000x reference)
#include <cuda_runtime.h>

static constexpr int IMG   = 128;
static constexpr int NPIX  = IMG * IMG;      // 16384
static constexpr int CH    = 64;
static constexpr int NHEAD = 8;
static constexpr int HIDN  = 128;
static constexpr float LNEPS  = 1e-5f;
static constexpr float QSCALE = 0.35355339059327373f;   // 8^-0.5

// ---------------- scratch (no allocations allowed) ----------------
__device__ __align__(16) float g_q[NHEAD * NPIX * 8];
__device__ __align__(16) float g_k[NHEAD * NPIX * 8];
__device__ __align__(16) float g_v[NHEAD * NPIX * 8];
__device__ float g_att[CH * NPIX];
__device__ float g_x1 [CH * NPIX];
__device__ float g_y  [CH * NPIX];
__device__ float g_h1 [HIDN * NPIX];

// ---------------- packed f32x2 helpers ----------------
typedef unsigned long long ull;

#define FMA2(acc, a, b) asm("fma.rn.f32x2 %0, %1, %2, %0;" : "+l"(acc) : "l"(a), "l"(b))

__device__ __forceinline__ ull pk(float lo, float hi) {
    ull r; asm("mov.b64 %0, {%1, %2};" : "=l"(r) : "f"(lo), "f"(hi)); return r;
}
__device__ __forceinline__ float2 upk(ull v) {
    float2 r; asm("mov.b64 {%0, %1}, %2;" : "=f"(r.x), "=f"(r.y) : "l"(v)); return r;
}

// weight smem swizzle: word index for output o (within a 64-wide group), input c:
//   s = o>>4, jj = (o>>2)&3, e = o&3  ->  c*W + (group_base) + jj*16 + s*4 + e
// so the 4 slices' LDS.128 for a given jj are 4 consecutive 16B lines (64B, conflict-free).

// =================================================================
// Kernel A: LN1 -> QKV -> qLN, kLN -> store q/k/v [head][pixel][8]
// block: 256 = 64 pixels x 4 slices.  grid: 256
// =================================================================
static constexpr int SMEM_A = (192 * 64 + 64 * 64) * 4;   // 65536 B

__global__ void __launch_bounds__(256)
kA(const float* __restrict__ x, const float* __restrict__ n1w, const float* __restrict__ n1b,
   const float* __restrict__ qkvw, const float* __restrict__ qkvb,
   const float* __restrict__ qnw, const float* __restrict__ qnb,
   const float* __restrict__ knw, const float* __restrict__ knb)
{
    extern __shared__ float smA[];
    float* wt = smA;              // swizzled [c][192]
    float* xs = smA + 192 * 64;   // xs[c*64 + px]
    const int tid = threadIdx.x;
    const int s = tid & 3, px = tid >> 2;
    const int p0 = blockIdx.x * 64;
    const int p = p0 + px;

    for (int i = tid; i < 192 * 64; i += 256) {
        int o = i >> 6, c = i & 63;
        int ph = o >> 6, ol = o & 63;
        int ss = ol >> 4, jj = (ol >> 2) & 3, e = ol & 3;
        wt[c * 192 + ph * 64 + jj * 16 + ss * 4 + e] = qkvw[i];
    }
    for (int i = tid; i < 64 * 64; i += 256) {
        int c = i >> 6, pp = i & 63;
        xs[c * 64 + pp] = x[c * NPIX + p0 + pp];
    }
    __syncthreads();

    // ---- LN1 (4 lanes per pixel cooperate) ----
    float mean = 0.f;
    #pragma unroll
    for (int j = 0; j < 16; j++) mean += xs[(s * 16 + j) * 64 + px];
    mean += __shfl_xor_sync(0xffffffffu, mean, 1);
    mean += __shfl_xor_sync(0xffffffffu, mean, 2);
    mean *= (1.f / 64);
    float var = 0.f;
    #pragma unroll
    for (int j = 0; j < 16; j++) { float d = xs[(s * 16 + j) * 64 + px] - mean; var += d * d; }
    var += __shfl_xor_sync(0xffffffffu, var, 1);
    var += __shfl_xor_sync(0xffffffffu, var, 2);
    float inv = rsqrtf(var * (1.f / 64) + LNEPS);
    #pragma unroll
    for (int j = 0; j < 16; j++) {
        int c = s * 16 + j;
        xs[c * 64 + px] = (xs[c * 64 + px] - mean) * inv * n1w[c] + n1b[c];
    }
    __syncthreads();

    // ---- GEMV: 48 outputs per thread (16 q, 16 k, 16 v), packed pairs ----
    ull acc2[24];
    #pragma unroll
    for (int i = 0; i < 24; i++) acc2[i] = 0ull;

    #pragma unroll 2
    for (int c = 0; c < 64; c++) {
        float xc = xs[c * 64 + px];
        ull xx = pk(xc, xc);
        const float* wc = wt + c * 192 + s * 4;
        #pragma unroll
        for (int ph = 0; ph < 3; ph++) {
            #pragma unroll
            for (int jj = 0; jj < 4; jj++) {
                ulonglong2 w2 = *reinterpret_cast<const ulonglong2*>(wc + ph * 64 + jj * 16);
                FMA2(acc2[ph * 8 + jj * 2],     w2.x, xx);
                FMA2(acc2[ph * 8 + jj * 2 + 1], w2.y, xx);
            }
        }
    }

    float v16[16];

    // ---------------- Q: bias + LN + scale + store ----------------
    {
        #pragma unroll
        for (int jj = 0; jj < 4; jj++) {
            float2 f01 = upk(acc2[jj * 2]), f23 = upk(acc2[jj * 2 + 1]);
            v16[jj*4+0] = f01.x; v16[jj*4+1] = f01.y; v16[jj*4+2] = f23.x; v16[jj*4+3] = f23.y;
        }
        float m2 = 0.f;
        #pragma unroll
        for (int j = 0; j < 16; j++) { v16[j] += qkvb[s * 16 + j]; m2 += v16[j]; }
        m2 += __shfl_xor_sync(0xffffffffu, m2, 1);
        m2 += __shfl_xor_sync(0xffffffffu, m2, 2);
        m2 *= (1.f / 64);
        float v2 = 0.f;
        #pragma unroll
        for (int j = 0; j < 16; j++) { float d = v16[j] - m2; v2 += d * d; }
        v2 += __shfl_xor_sync(0xffffffffu, v2, 1);
        v2 += __shfl_xor_sync(0xffffffffu, v2, 2);
        float iv = rsqrtf(v2 * (1.f / 64) + LNEPS);
        #pragma unroll
        for (int j = 0; j < 16; j++) {
            int ch = s * 16 + j;
            v16[j] = ((v16[j] - m2) * iv * qnw[ch] + qnb[ch]) * QSCALE;
        }
        float4* d0 = reinterpret_cast<float4*>(&g_q[((2 * s) * NPIX + p) * 8]);
        d0[0] = make_float4(v16[0], v16[1], v16[2], v16[3]);
        d0[1] = make_float4(v16[4], v16[5], v16[6], v16[7]);
        float4* d1 = reinterpret_cast<float4*>(&g_q[((2 * s + 1) * NPIX + p) * 8]);
        d1[0] = make_float4(v16[8], v16[9], v16[10], v16[11]);
        d1[1] = make_float4(v16[12], v16[13], v16[14], v16[15]);
    }

    // ---------------- K: bias + LN + store ----------------
    {
        #pragma unroll
        for (int jj = 0; jj < 4; jj++) {
            float2 f01 = upk(acc2[8 + jj * 2]), f23 = upk(acc2[8 + jj * 2 + 1]);
            v16[jj*4+0] = f01.x; v16[jj*4+1] = f01.y; v16[jj*4+2] = f23.x; v16[jj*4+3] = f23.y;
        }
        float m2 = 0.f;
        #pragma unroll
        for (int j = 0; j < 16; j++) { v16[j] += qkvb[64 + s * 16 + j]; m2 += v16[j]; }
        m2 += __shfl_xor_sync(0xffffffffu, m2, 1);
        m2 += __shfl_xor_sync(0xffffffffu, m2, 2);
        m2 *= (1.f / 64);
        float v2 = 0.f;
        #pragma unroll
        for (int j = 0; j < 16; j++) { float d = v16[j] - m2; v2 += d * d; }
        v2 += __shfl_xor_sync(0xffffffffu, v2, 1);
        v2 += __shfl_xor_sync(0xffffffffu, v2, 2);
        float iv = rsqrtf(v2 * (1.f / 64) + LNEPS);
        #pragma unroll
        for (int j = 0; j < 16; j++) {
            int ch = s * 16 + j;
            v16[j] = (v16[j] - m2) * iv * knw[ch] + knb[ch];
        }
        float4* d0 = reinterpret_cast<float4*>(&g_k[((2 * s) * NPIX + p) * 8]);
        d0[0] = make_float4(v16[0], v16[1], v16[2], v16[3]);
        d0[1] = make_float4(v16[4], v16[5], v16[6], v16[7]);
        float4* d1 = reinterpret_cast<float4*>(&g_k[((2 * s + 1) * NPIX + p) * 8]);
        d1[0] = make_float4(v16[8], v16[9], v16[10], v16[11]);
        d1[1] = make_float4(v16[12], v16[13], v16[14], v16[15]);
    }

    // ---------------- V: bias + store ----------------
    {
        #pragma unroll
        for (int jj = 0; jj < 4; jj++) {
            float2 f01 = upk(acc2[16 + jj * 2]), f23 = upk(acc2[16 + jj * 2 + 1]);
            v16[jj*4+0] = f01.x; v16[jj*4+1] = f01.y; v16[jj*4+2] = f23.x; v16[jj*4+3] = f23.y;
        }
        #pragma unroll
        for (int j = 0; j < 16; j++) v16[j] += qkvb[128 + s * 16 + j];
        float4* d0 = reinterpret_cast<float4*>(&g_v[((2 * s) * NPIX + p) * 8]);
        d0[0] = make_float4(v16[0], v16[1], v16[2], v16[3]);
        d0[1] = make_float4(v16[4], v16[5], v16[6], v16[7]);
        float4* d1 = reinterpret_cast<float4*>(&g_v[((2 * s + 1) * NPIX + p) * 8]);
        d1[0] = make_float4(v16[8], v16[9], v16[10], v16[11]);
        d1[1] = make_float4(v16[12], v16[13], v16[14], v16[15]);
    }
}

// =================================================================
// Kernel B: neighborhood attention, float4 planes + no-max softmax
// =================================================================
static constexpr int PLANE  = 44 * 45;            // float4 elements per plane
static constexpr int SMEM_B = 4 * PLANE * 16;     // 126720 B

__global__ void __launch_bounds__(256)
kB()
{
    extern __shared__ float4 smf4[];   // planes: K d0-3, K d4-7, V d0-3, V d4-7
    const int tile = blockIdx.x, head = blockIdx.y;
    const int th0 = (tile >> 3) << 4, tw0 = (tile & 7) << 4;
    const int tid = threadIdx.x;
    const float* kg = g_k + head * (NPIX * 8);
    const float* vg = g_v + head * (NPIX * 8);

    for (int e = tid; e < 2 * 44 * 44; e += 256) {
        int arr = (e >= 44 * 44) ? 1 : 0;
        int i = e - arr * (44 * 44);
        int r = i / 44, col = i - r * 44;
        int hh = min(max(th0 - 16 + r, 0), 127);
        int ww = min(max(tw0 - 16 + col, 0), 127);
        const float4* src = reinterpret_cast<const float4*>((arr ? vg : kg) + (hh * 128 + ww) * 8);
        smf4[(arr * 2)     * PLANE + r * 45 + col] = src[0];
        smf4[(arr * 2 + 1) * PLANE + r * 45 + col] = src[1];
    }
    __syncthreads();

    const int qy = tid >> 4, qx = tid & 15;
    const int h = th0 + qy, w = tw0 + qx;
    const int p = h * 128 + w;

    ulonglong2 qa = *reinterpret_cast<const ulonglong2*>(&g_q[(head * NPIX + p) * 8]);
    ulonglong2 qb = *reinterpret_cast<const ulonglong2*>(&g_q[(head * NPIX + p) * 8 + 4]);

    float l = 0.f;
    ull acc2[4] = {0ull, 0ull, 0ull, 0ull};

    #pragma unroll
    for (int a = 0; a < 8; a++) {
        int oh = 4 * a - 16;
        bool vh = (unsigned)(h + oh) < 128u;
        int rb = (qy + 16 + oh) * 45 + qx + 16;
        #pragma unroll
        for (int b = 0; b < 8; b++) {
            int ow = 4 * b - 16;
            bool ok = vh && ((unsigned)(w + ow) < 128u);
            int off = rb + ow;
            ulonglong2 k01 = *reinterpret_cast<const ulonglong2*>(&smf4[off]);
            ulonglong2 k23 = *reinterpret_cast<const ulonglong2*>(&smf4[PLANE + off]);
            ull s2 = 0ull;
            FMA2(s2, k01.x, qa.x);
            FMA2(s2, k01.y, qa.y);
            FMA2(s2, k23.x, qb.x);
            FMA2(s2, k23.y, qb.y);
            float2 sf = upk(s2);
            float sc = ok ? (sf.x + sf.y) : -1e30f;
            float ee = __expf(sc);
            l += ee;
            ull e2 = pk(ee, ee);
            ulonglong2 v01 = *reinterpret_cast<const ulonglong2*>(&smf4[2 * PLANE + off]);
            ulonglong2 v23 = *reinterpret_cast<const ulonglong2*>(&smf4[3 * PLANE + off]);
            FMA2(acc2[0], v01.x, e2);
            FMA2(acc2[1], v01.y, e2);
            FMA2(acc2[2], v23.x, e2);
            FMA2(acc2[3], v23.y, e2);
        }
    }
    float rl = 1.0f / l;
    #pragma unroll
    for (int i = 0; i < 4; i++) {
        float2 f = upk(acc2[i]);
        g_att[(head * 8 + 2 * i)     * NPIX + p] = f.x * rl;
        g_att[(head * 8 + 2 * i + 1) * NPIX + p] = f.y * rl;
    }
}

// =================================================================
// Kernel C: proj + gamma1*o + residual -> x1; LN2 -> y
// =================================================================
__global__ void __launch_bounds__(256)
kC(const float* __restrict__ x, const float* __restrict__ projw, const float* __restrict__ projb,
   const float* __restrict__ g1, const float* __restrict__ n2w, const float* __restrict__ n2b)
{
    __shared__ float wt[64 * 64];
    __shared__ float as[64 * 64];
    const int tid = threadIdx.x;
    const int s = tid & 3, px = tid >> 2;
    const int p0 = blockIdx.x * 64;
    const int p = p0 + px;

    for (int i = tid; i < 64 * 64; i += 256) {
        int o = i >> 6, c = i & 63;
        int ss = o >> 4, jj = (o >> 2) & 3, e = o & 3;
        wt[c * 64 + jj * 16 + ss * 4 + e] = projw[i];
    }
    for (int i = tid; i < 64 * 64; i += 256) {
        int c = i >> 6, pp = i & 63;
        as[c * 64 + pp] = g_att[c * NPIX + p0 + pp];
    }
    __syncthreads();

    ull acc2[8];
    #pragma unroll
    for (int i = 0; i < 8; i++) acc2[i] = 0ull;
    #pragma unroll 4
    for (int c = 0; c < 64; c++) {
        float a = as[c * 64 + px];
        ull aa = pk(a, a);
        const float* wc = wt + c * 64 + s * 4;
        #pragma unroll
        for (int jj = 0; jj < 4; jj++) {
            ulonglong2 w2 = *reinterpret_cast<const ulonglong2*>(wc + jj * 16);
            FMA2(acc2[jj * 2],     w2.x, aa);
            FMA2(acc2[jj * 2 + 1], w2.y, aa);
        }
    }

    float xv[16];
    float mean = 0.f;
    #pragma unroll
    for (int jj = 0; jj < 4; jj++) {
        float2 f01 = upk(acc2[jj * 2]), f23 = upk(acc2[jj * 2 + 1]);
        float t[4] = {f01.x, f01.y, f23.x, f23.y};
        #pragma unroll
        for (int e = 0; e < 4; e++) {
            int j = jj * 4 + e, ch = s * 16 + j;
            float v = x[ch * NPIX + p] + g1[ch] * (t[e] + projb[ch]);
            g_x1[ch * NPIX + p] = v;
            xv[j] = v;
            mean += v;
        }
    }
    mean += __shfl_xor_sync(0xffffffffu, mean, 1);
    mean += __shfl_xor_sync(0xffffffffu, mean, 2);
    mean *= (1.f / 64);
    float var = 0.f;
    #pragma unroll
    for (int j = 0; j < 16; j++) { float d = xv[j] - mean; var += d * d; }
    var += __shfl_xor_sync(0xffffffffu, var, 1);
    var += __shfl_xor_sync(0xffffffffu, var, 2);
    float inv = rsqrtf(var * (1.f / 64) + LNEPS);
    #pragma unroll
    for (int j = 0; j < 16; j++) {
        int ch = s * 16 + j;
        g_y[ch * NPIX + p] = (xv[j] - mean) * inv * n2w[ch] + n2b[ch];
    }
}

// =================================================================
// Kernel D: fc1 + LN + SiLU -> h1
// =================================================================
static constexpr int SMEM_D = (128 * 64 + 64 * 64) * 4;   // 49152 B

__global__ void __launch_bounds__(256)
kD(const float* __restrict__ fc1w, const float* __restrict__ fc1b,
   const float* __restrict__ mnw, const float* __restrict__ mnb)
{
    extern __shared__ float smD[];
    float* wt = smD;                 // swizzled [c][128]
    float* ys = smD + 128 * 64;      // ys[c*64 + px]
    const int tid = threadIdx.x;
    const int s = tid & 3, px = tid >> 2;
    const int p0 = blockIdx.x * 64;
    const int p = p0 + px;

    for (int i = tid; i < 128 * 64; i += 256) {
        int o = i >> 6, c = i & 63;
        int ss = o >> 5, jj = (o >> 2) & 7, e = o & 3;
        wt[c * 128 + jj * 16 + ss * 4 + e] = fc1w[i];
    }
    for (int i = tid; i < 64 * 64; i += 256) {
        int c = i >> 6, pp = i & 63;
        ys[c * 64 + pp] = g_y[c * NPIX + p0 + pp];
    }
    __syncthreads();

    ull acc2[16];
    #pragma unroll
    for (int i = 0; i < 16; i++) acc2[i] = 0ull;
    #pragma unroll 2
    for (int c = 0; c < 64; c++) {
        float yv = ys[c * 64 + px];
        ull yy = pk(yv, yv);
        const float* wc = wt + c * 128 + s * 4;
        #pragma unroll
        for (int jj = 0; jj < 8; jj++) {
            ulonglong2 w2 = *reinterpret_cast<const ulonglong2*>(wc + jj * 16);
            FMA2(acc2[jj * 2],     w2.x, yy);
            FMA2(acc2[jj * 2 + 1], w2.y, yy);
        }
    }

    float v32[32];
    #pragma unroll
    for (int jj = 0; jj < 8; jj++) {
        float2 f01 = upk(acc2[jj * 2]), f23 = upk(acc2[jj * 2 + 1]);
        v32[jj*4+0] = f01.x; v32[jj*4+1] = f01.y; v32[jj*4+2] = f23.x; v32[jj*4+3] = f23.y;
    }
    float mean = 0.f;
    #pragma unroll
    for (int j = 0; j < 32; j++) { v32[j] += fc1b[s * 32 + j]; mean += v32[j]; }
    mean += __shfl_xor_sync(0xffffffffu, mean, 1);
    mean += __shfl_xor_sync(0xffffffffu, mean, 2);
    mean *= (1.f / 128);
    float var = 0.f;
    #pragma unroll
    for (int j = 0; j < 32; j++) { float d = v32[j] - mean; var += d * d; }
    var += __shfl_xor_sync(0xffffffffu, var, 1);
    var += __shfl_xor_sync(0xffffffffu, var, 2);
    float inv = rsqrtf(var * (1.f / 128) + LNEPS);
    #pragma unroll
    for (int j = 0; j < 32; j++) {
        int o = s * 32 + j;
        float hh = (v32[j] - mean) * inv * mnw[o] + mnb[o];
        g_h1[o * NPIX + p] = hh / (1.f + __expf(-hh));
    }
}

// =================================================================
// Kernel E: fc2 + gamma2 + residual -> out
// =================================================================
static constexpr int SMEM_E = (128 * 64 + 128 * 64) * 4;   // 65536 B

__global__ void __launch_bounds__(256)
kE(const float* __restrict__ fc2w, const float* __restrict__ fc2b,
   const float* __restrict__ g2, float* __restrict__ out)
{
    extern __shared__ float smE[];
    float* wt = smE;                 // swizzled [c][64], c<128
    float* hs = smE + 128 * 64;      // hs[c*64 + px], c<128
    const int tid = threadIdx.x;
    const int s = tid & 3, px = tid >> 2;
    const int p0 = blockIdx.x * 64;
    const int p = p0 + px;

    for (int i = tid; i < 64 * 128; i += 256) {
        int o = i >> 7, c = i & 127;
        int ss = o >> 4, jj = (o >> 2) & 3, e = o & 3;
        wt[c * 64 + jj * 16 + ss * 4 + e] = fc2w[i];
    }
    for (int i = tid; i < 128 * 64; i += 256) {
        int c = i >> 6, pp = i & 63;
        hs[c * 64 + pp] = g_h1[c * NPIX + p0 + pp];
    }
    __syncthreads();

    ull acc2[8];
    #pragma unroll
    for (int i = 0; i < 8; i++) acc2[i] = 0ull;
    #pragma unroll 4
    for (int c = 0; c < 128; c++) {
        float hv = hs[c * 64 + px];
        ull hh = pk(hv, hv);
        const float* wc = wt + c * 64 + s * 4;
        #pragma unroll
        for (int jj = 0; jj < 4; jj++) {
            ulonglong2 w2 = *reinterpret_cast<const ulonglong2*>(wc + jj * 16);
            FMA2(acc2[jj * 2],     w2.x, hh);
            FMA2(acc2[jj * 2 + 1], w2.y, hh);
        }
    }

    #pragma unroll
    for (int jj = 0; jj < 4; jj++) {
        float2 f01 = upk(acc2[jj * 2]), f23 = upk(acc2[jj * 2 + 1]);
        float t[4] = {f01.x, f01.y, f23.x, f23.y};
        #pragma unroll
        for (int e = 0; e < 4; e++) {
            int ch = s * 16 + jj * 4 + e;
            out[ch * NPIX + p] = g_x1[ch * NPIX + p] + g2[ch] * (t[e] + fc2b[ch]);
        }
    }
}

// =================================================================
extern "C" void kernel_launch(void* const* d_in, const int* in_sizes, int n_in,
                              void* d_out, int out_size)
{
    const float* x     = (const float*)d_in[0];
    const float* n1w   = (const float*)d_in[1];
    const float* n1b   = (const float*)d_in[2];
    const float* qkvw  = (const float*)d_in[3];
    const float* qkvb  = (const float*)d_in[4];
    const float* qnw   = (const float*)d_in[5];
    const float* qnb   = (const float*)d_in[6];
    const float* knw   = (const float*)d_in[7];
    const float* knb   = (const float*)d_in[8];
    const float* projw = (const float*)d_in[9];
    const float* projb = (const float*)d_in[10];
    const float* g1    = (const float*)d_in[11];
    const float* n2w   = (const float*)d_in[12];
    const float* n2b   = (const float*)d_in[13];
    const float* fc1w  = (const float*)d_in[14];
    const float* fc1b  = (const float*)d_in[15];
    const float* mnw   = (const float*)d_in[16];
    const float* mnb   = (const float*)d_in[17];
    const float* fc2w  = (const float*)d_in[18];
    const float* fc2b  = (const float*)d_in[19];
    const float* g2    = (const float*)d_in[20];
    float* out = (float*)d_out;

    cudaFuncSetAttribute(kA, cudaFuncAttributeMaxDynamicSharedMemorySize, SMEM_A);
    cudaFuncSetAttribute(kB, cudaFuncAttributeMaxDynamicSharedMemorySize, SMEM_B);
    cudaFuncSetAttribute(kD, cudaFuncAttributeMaxDynamicSharedMemorySize, SMEM_D);
    cudaFuncSetAttribute(kE, cudaFuncAttributeMaxDynamicSharedMemorySize, SMEM_E);

    kA<<<256, 256, SMEM_A>>>(x, n1w, n1b, qkvw, qkvb, qnw, qnb, knw, knb);
    kB<<<dim3(64, 8), 256, SMEM_B>>>();
    kC<<<256, 256>>>(x, projw, projb, g1, n2w, n2b);
    kD<<<256, 256, SMEM_D>>>(fc1w, fc1b, mnw, mnb);
    kE<<<256, 256, SMEM_E>>>(fc2w, fc2b, g2, out);
}

// round 3
// speedup vs baseline: 1.5884x; 1.5884x over previous
#include <cuda_runtime.h>

typedef unsigned long long ull;

static constexpr int IMG   = 128;
static constexpr int NPIX  = IMG * IMG;      // 16384
static constexpr int CH    = 64;
static constexpr int NHEAD = 8;
static constexpr int HIDN  = 128;
static constexpr float LNEPS  = 1e-5f;
static constexpr float QSCALE = 0.35355339059327373f;   // 8^-0.5

// ---------------- scratch ----------------
__device__ __align__(16) float g_q[NHEAD * NPIX * 8];
__device__ __align__(16) float g_k[NHEAD * NPIX * 8];
__device__ __align__(16) float g_v[NHEAD * NPIX * 8];
__device__ __align__(16) float g_att[CH * NPIX];
__device__ __align__(16) float g_x1 [CH * NPIX];
__device__ __align__(16) float g_y  [CH * NPIX];
__device__ __align__(16) float g_h1 [HIDN * NPIX];

// ---------------- packed f32x2 helpers ----------------
#define FMA2(acc, a, b) asm("fma.rn.f32x2 %0, %1, %2, %0;" : "+l"(acc) : "l"(a), "l"(b))

__device__ __forceinline__ ull pk(float lo, float hi) {
    ull r; asm("mov.b64 %0, {%1, %2};" : "=l"(r) : "f"(lo), "f"(hi)); return r;
}
__device__ __forceinline__ float2 upk(ull v) {
    float2 r; asm("mov.b64 {%0, %1}, %2;" : "=f"(r.x), "=f"(r.y) : "l"(v)); return r;
}

// =================================================================
// Kernel A: LN1 -> QKV GEMM (8x8 register tiles) -> qLN/kLN -> store
// block 384 = 24 out-tiles x 16 px-tiles; px-tile 128; grid 128
// =================================================================
static constexpr int WS_A = 196;   // wt row stride (floats)
static constexpr int QS_A = 132;   // qkv staging row stride
static constexpr int SMEM_A = (192 * QS_A > 64 * 128 + 64 * WS_A ?
                               192 * QS_A : 64 * 128 + 64 * WS_A) * 4;  // 101376

__global__ void __launch_bounds__(384)
kA(const float* __restrict__ x, const float* __restrict__ n1w, const float* __restrict__ n1b,
   const float* __restrict__ qkvw, const float* __restrict__ qkvb,
   const float* __restrict__ qnw, const float* __restrict__ qnb,
   const float* __restrict__ knw, const float* __restrict__ knb)
{
    extern __shared__ float sm[];
    float* xs = sm;              // [64][128]
    float* wt = sm + 64 * 128;   // [64][WS_A]
    float* qs = sm;              // staging [192][QS_A] (reused after GEMM)
    const int tid = threadIdx.x;
    const int p0 = blockIdx.x * 128;

    // stage weights transposed: wt[c][o] = qkvw[o][c]
    for (int i = tid; i < 192 * 64; i += 384) {
        int o = i >> 6, c = i & 63;
        wt[c * WS_A + o] = qkvw[i];
    }
    // stage x
    for (int i = tid; i < 64 * 128; i += 384) {
        int c = i >> 7, pp = i & 127;
        xs[c * 128 + pp] = x[c * NPIX + p0 + pp];
    }
    __syncthreads();

    // LN1: one thread per pixel
    if (tid < 128) {
        float mean = 0.f;
        #pragma unroll
        for (int c = 0; c < 64; c++) mean += xs[c * 128 + tid];
        mean *= (1.f / 64);
        float var = 0.f;
        #pragma unroll
        for (int c = 0; c < 64; c++) { float d = xs[c * 128 + tid] - mean; var += d * d; }
        float inv = rsqrtf(var * (1.f / 64) + LNEPS);
        #pragma unroll
        for (int c = 0; c < 64; c++)
            xs[c * 128 + tid] = (xs[c * 128 + tid] - mean) * inv * n1w[c] + n1b[c];
    }
    __syncthreads();

    // GEMM: thread tile 8 outs x 8 px
    const int ot = tid >> 4;        // 0..23
    const int pt = tid & 15;        // 0..15
    ull acc2[8][4];
    #pragma unroll
    for (int oi = 0; oi < 8; oi++)
        #pragma unroll
        for (int pj = 0; pj < 4; pj++) acc2[oi][pj] = 0ull;

    #pragma unroll 4
    for (int c = 0; c < 64; c++) {
        float4 w0 = *reinterpret_cast<const float4*>(&wt[c * WS_A + ot * 8]);
        float4 w1 = *reinterpret_cast<const float4*>(&wt[c * WS_A + ot * 8 + 4]);
        ulonglong2 xa = *reinterpret_cast<const ulonglong2*>(&xs[c * 128 + pt * 8]);
        ulonglong2 xb = *reinterpret_cast<const ulonglong2*>(&xs[c * 128 + pt * 8 + 4]);
        ull xp0 = xa.x, xp1 = xa.y, xp2 = xb.x, xp3 = xb.y;
        float wf[8] = {w0.x, w0.y, w0.z, w0.w, w1.x, w1.y, w1.z, w1.w};
        #pragma unroll
        for (int oi = 0; oi < 8; oi++) {
            ull wp = pk(wf[oi], wf[oi]);
            FMA2(acc2[oi][0], wp, xp0);
            FMA2(acc2[oi][1], wp, xp1);
            FMA2(acc2[oi][2], wp, xp2);
            FMA2(acc2[oi][3], wp, xp3);
        }
    }
    __syncthreads();   // done reading xs/wt

    #pragma unroll
    for (int oi = 0; oi < 8; oi++) {
        int o = ot * 8 + oi;
        #pragma unroll
        for (int pj = 0; pj < 4; pj++)
            *reinterpret_cast<ull*>(&qs[o * QS_A + pt * 8 + 2 * pj]) = acc2[oi][pj];
    }
    __syncthreads();

    // stage 3: per (array, pixel) LN + store
    const int arr = tid >> 7;       // 0,1,2
    const int px  = tid & 127;
    const int p   = p0 + px;
    float vv[64];
    #pragma unroll
    for (int j = 0; j < 64; j++)
        vv[j] = qs[(arr * 64 + j) * QS_A + px] + qkvb[arr * 64 + j];

    if (arr < 2) {
        float mean = 0.f;
        #pragma unroll
        for (int j = 0; j < 64; j++) mean += vv[j];
        mean *= (1.f / 64);
        float var = 0.f;
        #pragma unroll
        for (int j = 0; j < 64; j++) { float d = vv[j] - mean; var += d * d; }
        float inv = rsqrtf(var * (1.f / 64) + LNEPS);
        const float* lw = arr ? knw : qnw;
        const float* lb = arr ? knb : qnb;
        float sc = arr ? 1.0f : QSCALE;
        #pragma unroll
        for (int j = 0; j < 64; j++)
            vv[j] = ((vv[j] - mean) * inv * lw[j] + lb[j]) * sc;
    }
    float* dst = (arr == 0) ? g_q : (arr == 1) ? g_k : g_v;
    #pragma unroll
    for (int h8 = 0; h8 < 8; h8++) {
        float4* d4 = reinterpret_cast<float4*>(&dst[(h8 * NPIX + p) * 8]);
        d4[0] = make_float4(vv[h8*8+0], vv[h8*8+1], vv[h8*8+2], vv[h8*8+3]);
        d4[1] = make_float4(vv[h8*8+4], vv[h8*8+5], vv[h8*8+6], vv[h8*8+7]);
    }
}

// =================================================================
// Kernel B: neighborhood attention with 4-pixel quads (col sharing)
// tile 16 rows x 32 cols, halo 44x60, 128 threads
// =================================================================
static constexpr int HS_B = 62;                 // halo row stride (float4)
static constexpr int PL_B = 44 * HS_B;          // plane size (float4)
static constexpr int SMEM_B = 4 * PL_B * 16;    // 174592 B

__global__ void __launch_bounds__(128)
kB()
{
    extern __shared__ float4 sm4[];   // planes: K d0-3, K d4-7, V d0-3, V d4-7
    const int tile = blockIdx.x, head = blockIdx.y;
    const int th0 = (tile >> 2) * 16, tw0 = (tile & 3) * 32;
    const int tid = threadIdx.x;
    const float* kg = g_k + head * (NPIX * 8);
    const float* vg = g_v + head * (NPIX * 8);

    for (int e = tid; e < 2 * 44 * 60; e += 128) {
        int arr = (e >= 44 * 60) ? 1 : 0;
        int i = e - arr * (44 * 60);
        int r = i / 60, col = i - r * 60;
        int hh = min(max(th0 - 16 + r, 0), 127);
        int ww = min(max(tw0 - 16 + col, 0), 127);
        const float4* src = reinterpret_cast<const float4*>((arr ? vg : kg) + (hh * 128 + ww) * 8);
        sm4[(arr * 2)     * PL_B + r * HS_B + col] = src[0];
        sm4[(arr * 2 + 1) * PL_B + r * HS_B + col] = src[1];
    }
    __syncthreads();

    const int qy   = tid >> 3;                     // 0..15
    const int qx8  = tid & 7;
    const int wloc = (qx8 & 3) + ((qx8 >> 2) << 4); // 0..3, 16..19
    const int h  = th0 + qy;
    const int wb = tw0 + wloc;                      // quad pixels wb + 4t

    ulonglong2 qA[4], qB[4];
    #pragma unroll
    for (int t = 0; t < 4; t++) {
        const float* qp = &g_q[(head * NPIX + h * 128 + wb + 4 * t) * 8];
        qA[t] = *reinterpret_cast<const ulonglong2*>(qp);
        qB[t] = *reinterpret_cast<const ulonglong2*>(qp + 4);
    }

    float l[4] = {0.f, 0.f, 0.f, 0.f};
    ull acc2[4][4];
    #pragma unroll
    for (int t = 0; t < 4; t++)
        #pragma unroll
        for (int i = 0; i < 4; i++) acc2[t][i] = 0ull;

    #pragma unroll
    for (int a = 0; a < 8; a++) {
        int oh = 4 * a - 16;
        bool vr = (unsigned)(h + oh) < 128u;
        int rbase = (qy + 16 + oh) * HS_B;
        #pragma unroll
        for (int s = 0; s < 11; s++) {
            int off = rbase + wloc + 4 * s;
            bool ok = vr && ((unsigned)(wb + 4 * s - 16) < 128u);
            ulonglong2 k01 = *reinterpret_cast<const ulonglong2*>(&sm4[off]);
            ulonglong2 k23 = *reinterpret_cast<const ulonglong2*>(&sm4[PL_B + off]);
            ulonglong2 v01 = *reinterpret_cast<const ulonglong2*>(&sm4[2 * PL_B + off]);
            ulonglong2 v23 = *reinterpret_cast<const ulonglong2*>(&sm4[3 * PL_B + off]);
            #pragma unroll
            for (int t = 0; t < 4; t++) {
                if (t > s || t < s - 7) continue;
                ull s2 = 0ull;
                FMA2(s2, k01.x, qA[t].x);
                FMA2(s2, k01.y, qA[t].y);
                FMA2(s2, k23.x, qB[t].x);
                FMA2(s2, k23.y, qB[t].y);
                float2 sf = upk(s2);
                float sc = ok ? (sf.x + sf.y) : -1e30f;
                float ee = __expf(sc);
                l[t] += ee;
                ull e2 = pk(ee, ee);
                FMA2(acc2[t][0], v01.x, e2);
                FMA2(acc2[t][1], v01.y, e2);
                FMA2(acc2[t][2], v23.x, e2);
                FMA2(acc2[t][3], v23.y, e2);
            }
        }
    }
    #pragma unroll
    for (int t = 0; t < 4; t++) {
        float rl = 1.0f / l[t];
        int p = h * 128 + wb + 4 * t;
        #pragma unroll
        for (int i = 0; i < 4; i++) {
            float2 f = upk(acc2[t][i]);
            g_att[(head * 8 + 2 * i)     * NPIX + p] = f.x * rl;
            g_att[(head * 8 + 2 * i + 1) * NPIX + p] = f.y * rl;
        }
    }
}

// =================================================================
// Kernel C: proj GEMM + residual + LN2.  128 thr (8 ot x 16 pt)
// =================================================================
static constexpr int SMEM_C = (64 * 128 + 64 * 68) * 4;   // 50176

__global__ void __launch_bounds__(128)
kC(const float* __restrict__ x, const float* __restrict__ projw, const float* __restrict__ projb,
   const float* __restrict__ g1, const float* __restrict__ n2w, const float* __restrict__ n2b)
{
    extern __shared__ float sm[];
    float* as = sm;               // [64][128]
    float* wt = sm + 64 * 128;    // [64][68]
    float* rsum = sm;             // reused after GEMM: [128][9]
    float* rsq  = sm + 1152;
    float* mv   = sm + 2304;
    float* iv   = sm + 2432;
    const int tid = threadIdx.x;
    const int ot = tid >> 4, pt = tid & 15;
    const int p0 = blockIdx.x * 128;

    for (int i = tid; i < 64 * 64; i += 128) {
        int o = i >> 6, c = i & 63;
        wt[c * 68 + o] = projw[i];
    }
    for (int i = tid; i < 64 * 128; i += 128) {
        int c = i >> 7, pp = i & 127;
        as[c * 128 + pp] = g_att[c * NPIX + p0 + pp];
    }
    __syncthreads();

    ull acc2[8][4];
    #pragma unroll
    for (int oi = 0; oi < 8; oi++)
        #pragma unroll
        for (int pj = 0; pj < 4; pj++) acc2[oi][pj] = 0ull;

    #pragma unroll 4
    for (int c = 0; c < 64; c++) {
        float4 w0 = *reinterpret_cast<const float4*>(&wt[c * 68 + ot * 8]);
        float4 w1 = *reinterpret_cast<const float4*>(&wt[c * 68 + ot * 8 + 4]);
        ulonglong2 xa = *reinterpret_cast<const ulonglong2*>(&as[c * 128 + pt * 8]);
        ulonglong2 xb = *reinterpret_cast<const ulonglong2*>(&as[c * 128 + pt * 8 + 4]);
        float wf[8] = {w0.x, w0.y, w0.z, w0.w, w1.x, w1.y, w1.z, w1.w};
        #pragma unroll
        for (int oi = 0; oi < 8; oi++) {
            ull wp = pk(wf[oi], wf[oi]);
            FMA2(acc2[oi][0], wp, xa.x);
            FMA2(acc2[oi][1], wp, xa.y);
            FMA2(acc2[oi][2], wp, xb.x);
            FMA2(acc2[oi][3], wp, xb.y);
        }
    }
    __syncthreads();   // done with as/wt

    // x1 = x + g1*(o + pb); store; partial LN sums per pixel
    float x1v[8][8];
    float ps[8], pq[8];
    #pragma unroll
    for (int j = 0; j < 8; j++) { ps[j] = 0.f; pq[j] = 0.f; }
    #pragma unroll
    for (int oi = 0; oi < 8; oi++) {
        int ch = ot * 8 + oi;
        float pb = projb[ch], gg = g1[ch];
        const float* xr = &x[ch * NPIX + p0 + pt * 8];
        float4 xr0 = *reinterpret_cast<const float4*>(xr);
        float4 xr1 = *reinterpret_cast<const float4*>(xr + 4);
        float xf[8] = {xr0.x, xr0.y, xr0.z, xr0.w, xr1.x, xr1.y, xr1.z, xr1.w};
        #pragma unroll
        for (int pj = 0; pj < 4; pj++) {
            float2 f = upk(acc2[oi][pj]);
            float v0 = xf[2*pj]   + gg * (f.x + pb);
            float v1 = xf[2*pj+1] + gg * (f.y + pb);
            x1v[oi][2*pj] = v0; x1v[oi][2*pj+1] = v1;
            ps[2*pj] += v0;  ps[2*pj+1] += v1;
            pq[2*pj] += v0 * v0; pq[2*pj+1] += v1 * v1;
        }
        float4* d4 = reinterpret_cast<float4*>(&g_x1[ch * NPIX + p0 + pt * 8]);
        d4[0] = make_float4(x1v[oi][0], x1v[oi][1], x1v[oi][2], x1v[oi][3]);
        d4[1] = make_float4(x1v[oi][4], x1v[oi][5], x1v[oi][6], x1v[oi][7]);
    }
    #pragma unroll
    for (int j = 0; j < 8; j++) {
        rsum[(pt * 8 + j) * 9 + ot] = ps[j];
        rsq [(pt * 8 + j) * 9 + ot] = pq[j];
    }
    __syncthreads();
    if (tid < 128) {
        float s = 0.f, q = 0.f;
        #pragma unroll
        for (int k = 0; k < 8; k++) { s += rsum[tid * 9 + k]; q += rsq[tid * 9 + k]; }
        float mean = s * (1.f / 64);
        float var = q * (1.f / 64) - mean * mean;
        mv[tid] = mean;
        iv[tid] = rsqrtf(var + LNEPS);
    }
    __syncthreads();
    float mj[8], ij[8];
    #pragma unroll
    for (int j = 0; j < 8; j++) { mj[j] = mv[pt * 8 + j]; ij[j] = iv[pt * 8 + j]; }
    #pragma unroll
    for (int oi = 0; oi < 8; oi++) {
        int ch = ot * 8 + oi;
        float nw = n2w[ch], nb = n2b[ch];
        float y[8];
        #pragma unroll
        for (int j = 0; j < 8; j++) y[j] = (x1v[oi][j] - mj[j]) * ij[j] * nw + nb;
        float4* d4 = reinterpret_cast<float4*>(&g_y[ch * NPIX + p0 + pt * 8]);
        d4[0] = make_float4(y[0], y[1], y[2], y[3]);
        d4[1] = make_float4(y[4], y[5], y[6], y[7]);
    }
}

// =================================================================
// Kernel D: fc1 GEMM + LN + SiLU.  256 thr (16 ot x 16 pt)
// =================================================================
static constexpr int SMEM_D = (64 * 128 + 64 * 132) * 4;   // 66560

__global__ void __launch_bounds__(256)
kD(const float* __restrict__ fc1w, const float* __restrict__ fc1b,
   const float* __restrict__ mnw, const float* __restrict__ mnb)
{
    extern __shared__ float sm[];
    float* ys = sm;               // [64][128]
    float* wt = sm + 64 * 128;    // [64][132]
    float* rsum = sm;             // reused: [128][17]
    float* rsq  = sm + 2176;
    float* mv   = sm + 4352;
    float* iv   = sm + 4480;
    const int tid = threadIdx.x;
    const int ot = tid >> 4, pt = tid & 15;
    const int p0 = blockIdx.x * 128;

    for (int i = tid; i < 128 * 64; i += 256) {
        int o = i >> 6, c = i & 63;
        wt[c * 132 + o] = fc1w[i];
    }
    for (int i = tid; i < 64 * 128; i += 256) {
        int c = i >> 7, pp = i & 127;
        ys[c * 128 + pp] = g_y[c * NPIX + p0 + pp];
    }
    __syncthreads();

    ull acc2[8][4];
    #pragma unroll
    for (int oi = 0; oi < 8; oi++)
        #pragma unroll
        for (int pj = 0; pj < 4; pj++) acc2[oi][pj] = 0ull;

    #pragma unroll 4
    for (int c = 0; c < 64; c++) {
        float4 w0 = *reinterpret_cast<const float4*>(&wt[c * 132 + ot * 8]);
        float4 w1 = *reinterpret_cast<const float4*>(&wt[c * 132 + ot * 8 + 4]);
        ulonglong2 xa = *reinterpret_cast<const ulonglong2*>(&ys[c * 128 + pt * 8]);
        ulonglong2 xb = *reinterpret_cast<const ulonglong2*>(&ys[c * 128 + pt * 8 + 4]);
        float wf[8] = {w0.x, w0.y, w0.z, w0.w, w1.x, w1.y, w1.z, w1.w};
        #pragma unroll
        for (int oi = 0; oi < 8; oi++) {
            ull wp = pk(wf[oi], wf[oi]);
            FMA2(acc2[oi][0], wp, xa.x);
            FMA2(acc2[oi][1], wp, xa.y);
            FMA2(acc2[oi][2], wp, xb.x);
            FMA2(acc2[oi][3], wp, xb.y);
        }
    }
    __syncthreads();

    float hv[8][8];
    float ps[8], pq[8];
    #pragma unroll
    for (int j = 0; j < 8; j++) { ps[j] = 0.f; pq[j] = 0.f; }
    #pragma unroll
    for (int oi = 0; oi < 8; oi++) {
        float fb = fc1b[ot * 8 + oi];
        #pragma unroll
        for (int pj = 0; pj < 4; pj++) {
            float2 f = upk(acc2[oi][pj]);
            float v0 = f.x + fb, v1 = f.y + fb;
            hv[oi][2*pj] = v0; hv[oi][2*pj+1] = v1;
            ps[2*pj] += v0;  ps[2*pj+1] += v1;
            pq[2*pj] += v0 * v0; pq[2*pj+1] += v1 * v1;
        }
    }
    #pragma unroll
    for (int j = 0; j < 8; j++) {
        rsum[(pt * 8 + j) * 17 + ot] = ps[j];
        rsq [(pt * 8 + j) * 17 + ot] = pq[j];
    }
    __syncthreads();
    if (tid < 128) {
        float s = 0.f, q = 0.f;
        #pragma unroll
        for (int k = 0; k < 16; k++) { s += rsum[tid * 17 + k]; q += rsq[tid * 17 + k]; }
        float mean = s * (1.f / 128);
        float var = q * (1.f / 128) - mean * mean;
        mv[tid] = mean;
        iv[tid] = rsqrtf(var + LNEPS);
    }
    __syncthreads();
    float mj[8], ij[8];
    #pragma unroll
    for (int j = 0; j < 8; j++) { mj[j] = mv[pt * 8 + j]; ij[j] = iv[pt * 8 + j]; }
    #pragma unroll
    for (int oi = 0; oi < 8; oi++) {
        int ch = ot * 8 + oi;
        float nw = mnw[ch], nb = mnb[ch];
        float o8[8];
        #pragma unroll
        for (int j = 0; j < 8; j++) {
            float hh = (hv[oi][j] - mj[j]) * ij[j] * nw + nb;
            o8[j] = hh / (1.f + __expf(-hh));
        }
        float4* d4 = reinterpret_cast<float4*>(&g_h1[ch * NPIX + p0 + pt * 8]);
        d4[0] = make_float4(o8[0], o8[1], o8[2], o8[3]);
        d4[1] = make_float4(o8[4], o8[5], o8[6], o8[7]);
    }
}

// =================================================================
// Kernel E: fc2 GEMM + residual -> out.  128 thr (8 ot x 16 pt)
// =================================================================
static constexpr int SMEM_E = (128 * 128 + 128 * 68) * 4;   // 100352

__global__ void __launch_bounds__(128)
kE(const float* __restrict__ fc2w, const float* __restrict__ fc2b,
   const float* __restrict__ g2, float* __restrict__ out)
{
    extern __shared__ float sm[];
    float* hs = sm;                // [128][128]
    float* wt = sm + 128 * 128;    // [128][68]
    const int tid = threadIdx.x;
    const int ot = tid >> 4, pt = tid & 15;
    const int p0 = blockIdx.x * 128;

    for (int i = tid; i < 64 * 128; i += 128) {
        int o = i >> 7, c = i & 127;
        wt[c * 68 + o] = fc2w[i];
    }
    for (int i = tid; i < 128 * 128; i += 128) {
        int c = i >> 7, pp = i & 127;
        hs[c * 128 + pp] = g_h1[c * NPIX + p0 + pp];
    }
    __syncthreads();

    ull acc2[8][4];
    #pragma unroll
    for (int oi = 0; oi < 8; oi++)
        #pragma unroll
        for (int pj = 0; pj < 4; pj++) acc2[oi][pj] = 0ull;

    #pragma unroll 4
    for (int c = 0; c < 128; c++) {
        float4 w0 = *reinterpret_cast<const float4*>(&wt[c * 68 + ot * 8]);
        float4 w1 = *reinterpret_cast<const float4*>(&wt[c * 68 + ot * 8 + 4]);
        ulonglong2 xa = *reinterpret_cast<const ulonglong2*>(&hs[c * 128 + pt * 8]);
        ulonglong2 xb = *reinterpret_cast<const ulonglong2*>(&hs[c * 128 + pt * 8 + 4]);
        float wf[8] = {w0.x, w0.y, w0.z, w0.w, w1.x, w1.y, w1.z, w1.w};
        #pragma unroll
        for (int oi = 0; oi < 8; oi++) {
            ull wp = pk(wf[oi], wf[oi]);
            FMA2(acc2[oi][0], wp, xa.x);
            FMA2(acc2[oi][1], wp, xa.y);
            FMA2(acc2[oi][2], wp, xb.x);
            FMA2(acc2[oi][3], wp, xb.y);
        }
    }

    #pragma unroll
    for (int oi = 0; oi < 8; oi++) {
        int ch = ot * 8 + oi;
        float fb = fc2b[ch], gg = g2[ch];
        const float* xr = &g_x1[ch * NPIX + p0 + pt * 8];
        float4 xr0 = *reinterpret_cast<const float4*>(xr);
        float4 xr1 = *reinterpret_cast<const float4*>(xr + 4);
        float xf[8] = {xr0.x, xr0.y, xr0.z, xr0.w, xr1.x, xr1.y, xr1.z, xr1.w};
        float o8[8];
        #pragma unroll
        for (int pj = 0; pj < 4; pj++) {
            float2 f = upk(acc2[oi][pj]);
            o8[2*pj]   = xf[2*pj]   + gg * (f.x + fb);
            o8[2*pj+1] = xf[2*pj+1] + gg * (f.y + fb);
        }
        float4* d4 = reinterpret_cast<float4*>(&out[ch * NPIX + p0 + pt * 8]);
        d4[0] = make_float4(o8[0], o8[1], o8[2], o8[3]);
        d4[1] = make_float4(o8[4], o8[5], o8[6], o8[7]);
    }
}

// =================================================================
extern "C" void kernel_launch(void* const* d_in, const int* in_sizes, int n_in,
                              void* d_out, int out_size)
{
    const float* x     = (const float*)d_in[0];
    const float* n1w   = (const float*)d_in[1];
    const float* n1b   = (const float*)d_in[2];
    const float* qkvw  = (const float*)d_in[3];
    const float* qkvb  = (const float*)d_in[4];
    const float* qnw   = (const float*)d_in[5];
    const float* qnb   = (const float*)d_in[6];
    const float* knw   = (const float*)d_in[7];
    const float* knb   = (const float*)d_in[8];
    const float* projw = (const float*)d_in[9];
    const float* projb = (const float*)d_in[10];
    const float* g1    = (const float*)d_in[11];
    const float* n2w   = (const float*)d_in[12];
    const float* n2b   = (const float*)d_in[13];
    const float* fc1w  = (const float*)d_in[14];
    const float* fc1b  = (const float*)d_in[15];
    const float* mnw   = (const float*)d_in[16];
    const float* mnb   = (const float*)d_in[17];
    const float* fc2w  = (const float*)d_in[18];
    const float* fc2b  = (const float*)d_in[19];
    const float* g2    = (const float*)d_in[20];
    float* out = (float*)d_out;

    cudaFuncSetAttribute(kA, cudaFuncAttributeMaxDynamicSharedMemorySize, SMEM_A);
    cudaFuncSetAttribute(kB, cudaFuncAttributeMaxDynamicSharedMemorySize, SMEM_B);
    cudaFuncSetAttribute(kC, cudaFuncAttributeMaxDynamicSharedMemorySize, SMEM_C);
    cudaFuncSetAttribute(kD, cudaFuncAttributeMaxDynamicSharedMemorySize, SMEM_D);
    cudaFuncSetAttribute(kE, cudaFuncAttributeMaxDynamicSharedMemorySize, SMEM_E);

    kA<<<128, 384, SMEM_A>>>(x, n1w, n1b, qkvw, qkvb, qnw, qnb, knw, knb);
    kB<<<dim3(32, 8), 128, SMEM_B>>>();
    kC<<<128, 128, SMEM_C>>>(x, projw, projb, g1, n2w, n2b);
    kD<<<128, 256, SMEM_D>>>(fc1w, fc1b, mnw, mnb);
    kE<<<128, 128, SMEM_E>>>(fc2w, fc2b, g2, out);
}

// round 5
// speedup vs baseline: 2.2247x; 1.4006x over previous
#include <cuda_runtime.h>
#include <cuda_bf16.h>

typedef unsigned long long ull;
typedef unsigned int uint;

static constexpr int IMG   = 128;
static constexpr int NPIX  = IMG * IMG;      // 16384
static constexpr int CH    = 64;
static constexpr int NHEAD = 8;
static constexpr int HIDN  = 128;
static constexpr float LNEPS  = 1e-5f;
static constexpr float QSCALE = 0.35355339059327373f;   // 8^-0.5

// ---------------- scratch ----------------
__device__ __align__(16) float g_q[NHEAD * NPIX * 8];
__device__ __align__(16) unsigned short g_kb[NHEAD * NPIX * 8];   // bf16
__device__ __align__(16) unsigned short g_vb[NHEAD * NPIX * 8];   // bf16
__device__ __align__(16) float g_att[CH * NPIX];
__device__ __align__(16) float g_x1 [CH * NPIX];
__device__ __align__(16) float g_y  [CH * NPIX];
__device__ __align__(16) float g_h1 [HIDN * NPIX];

// ---------------- packed f32x2 helpers ----------------
#define FMA2(acc, a, b) asm("fma.rn.f32x2 %0, %1, %2, %0;" : "+l"(acc) : "l"(a), "l"(b))

__device__ __forceinline__ ull pk(float lo, float hi) {
    ull r; asm("mov.b64 %0, {%1, %2};" : "=l"(r) : "f"(lo), "f"(hi)); return r;
}
__device__ __forceinline__ float2 upk(ull v) {
    float2 r; asm("mov.b64 {%0, %1}, %2;" : "=f"(r.x), "=f"(r.y) : "l"(v)); return r;
}
__device__ __forceinline__ uint packbf(float a, float b) {
    __nv_bfloat162 h = __floats2bfloat162_rn(a, b);
    return *reinterpret_cast<uint*>(&h);
}
// bf16x2 word -> packed f32x2 (lo = bits<<16, hi = bits&0xffff0000)
__device__ __forceinline__ ull b2u(uint u) {
    return pk(__uint_as_float(u << 16), __uint_as_float(u & 0xffff0000u));
}

// =================================================================
// Kernel A: LN1 -> QKV GEMM -> qLN/kLN -> store q fp32, k/v bf16
// 64-px tiles, grid 256, block 384 = 24ot(8out) x 16pt(4px)
// =================================================================
static constexpr int SMEM_A = (64 * 68 + 64 * 196) * 4;   // 67584

__global__ void __launch_bounds__(384)
kA(const float* __restrict__ x, const float* __restrict__ n1w, const float* __restrict__ n1b,
   const float* __restrict__ qkvw, const float* __restrict__ qkvb,
   const float* __restrict__ qnw, const float* __restrict__ qnb,
   const float* __restrict__ knw, const float* __restrict__ knb)
{
    extern __shared__ float sm[];
    float* xs = sm;              // [64][68]
    float* wt = sm + 64 * 68;    // [64][196]
    float* qs = sm;              // staging [192][68] (reused)
    const int tid = threadIdx.x;
    const int p0 = blockIdx.x * 64;

    for (int i = tid; i < 192 * 64; i += 384) {
        int o = i >> 6, c = i & 63;
        wt[c * 196 + o] = qkvw[i];
    }
    for (int i = tid; i < 64 * 64; i += 384) {
        int c = i >> 6, pp = i & 63;
        xs[c * 68 + pp] = x[c * NPIX + p0 + pp];
    }
    __syncthreads();

    if (tid < 64) {
        float mean = 0.f;
        #pragma unroll
        for (int c = 0; c < 64; c++) mean += xs[c * 68 + tid];
        mean *= (1.f / 64);
        float var = 0.f;
        #pragma unroll
        for (int c = 0; c < 64; c++) { float d = xs[c * 68 + tid] - mean; var += d * d; }
        float inv = rsqrtf(var * (1.f / 64) + LNEPS);
        #pragma unroll
        for (int c = 0; c < 64; c++)
            xs[c * 68 + tid] = (xs[c * 68 + tid] - mean) * inv * n1w[c] + n1b[c];
    }
    __syncthreads();

    const int ot = tid >> 4;        // 0..23
    const int pt = tid & 15;        // 0..15
    ull acc2[8][2];
    #pragma unroll
    for (int oi = 0; oi < 8; oi++) { acc2[oi][0] = 0ull; acc2[oi][1] = 0ull; }

    #pragma unroll 4
    for (int c = 0; c < 64; c++) {
        float4 w0 = *reinterpret_cast<const float4*>(&wt[c * 196 + ot * 8]);
        float4 w1 = *reinterpret_cast<const float4*>(&wt[c * 196 + ot * 8 + 4]);
        ulonglong2 xa = *reinterpret_cast<const ulonglong2*>(&xs[c * 68 + pt * 4]);
        float wf[8] = {w0.x, w0.y, w0.z, w0.w, w1.x, w1.y, w1.z, w1.w};
        #pragma unroll
        for (int oi = 0; oi < 8; oi++) {
            ull wp = pk(wf[oi], wf[oi]);
            FMA2(acc2[oi][0], wp, xa.x);
            FMA2(acc2[oi][1], wp, xa.y);
        }
    }
    __syncthreads();   // done reading xs/wt

    #pragma unroll
    for (int oi = 0; oi < 8; oi++) {
        int o = ot * 8 + oi;
        *reinterpret_cast<ull*>(&qs[o * 68 + pt * 4])     = acc2[oi][0];
        *reinterpret_cast<ull*>(&qs[o * 68 + pt * 4 + 2]) = acc2[oi][1];
    }
    __syncthreads();

    if (tid < 192) {
        const int arr = tid >> 6;       // 0,1,2
        const int px  = tid & 63;
        const int p   = p0 + px;
        float vv[64];
        #pragma unroll
        for (int j = 0; j < 64; j++)
            vv[j] = qs[(arr * 64 + j) * 68 + px] + qkvb[arr * 64 + j];

        if (arr < 2) {
            float mean = 0.f;
            #pragma unroll
            for (int j = 0; j < 64; j++) mean += vv[j];
            mean *= (1.f / 64);
            float var = 0.f;
            #pragma unroll
            for (int j = 0; j < 64; j++) { float d = vv[j] - mean; var += d * d; }
            float inv = rsqrtf(var * (1.f / 64) + LNEPS);
            const float* lw = arr ? knw : qnw;
            const float* lb = arr ? knb : qnb;
            float sc = arr ? 1.0f : QSCALE;
            #pragma unroll
            for (int j = 0; j < 64; j++)
                vv[j] = ((vv[j] - mean) * inv * lw[j] + lb[j]) * sc;
        }
        if (arr == 0) {
            #pragma unroll
            for (int h8 = 0; h8 < 8; h8++) {
                float4* d4 = reinterpret_cast<float4*>(&g_q[(h8 * NPIX + p) * 8]);
                d4[0] = make_float4(vv[h8*8+0], vv[h8*8+1], vv[h8*8+2], vv[h8*8+3]);
                d4[1] = make_float4(vv[h8*8+4], vv[h8*8+5], vv[h8*8+6], vv[h8*8+7]);
            }
        } else {
            unsigned short* dst = (arr == 1) ? g_kb : g_vb;
            #pragma unroll
            for (int h8 = 0; h8 < 8; h8++) {
                uint4 u;
                u.x = packbf(vv[h8*8+0], vv[h8*8+1]);
                u.y = packbf(vv[h8*8+2], vv[h8*8+3]);
                u.z = packbf(vv[h8*8+4], vv[h8*8+5]);
                u.w = packbf(vv[h8*8+6], vv[h8*8+7]);
                *reinterpret_cast<uint4*>(&dst[(h8 * NPIX + p) * 8]) = u;
            }
        }
    }
}

// =================================================================
// Kernel B: neighborhood attention, bf16 K/V halo, 4-px quads
// tile 16x32, halo 44x60 (stride 67, swizzled), 128 threads
// =================================================================
static constexpr int HS_B = 67;                       // halo row stride (uint4)
static constexpr int PL_B = 44 * HS_B;                // plane (uint4)
static constexpr int SMEM_B = 2 * PL_B * 16;          // 94336 B

__device__ __forceinline__ int bswz(int c) { return c ^ (((c >> 4) & 1) << 2); }

__global__ void __launch_bounds__(128)
kB()
{
    extern __shared__ uint4 smu[];   // [0..PL_B) = K, [PL_B..2PL_B) = V
    const int tile = blockIdx.x, head = blockIdx.y;
    const int th0 = (tile >> 2) * 16, tw0 = (tile & 3) * 32;
    const int tid = threadIdx.x;
    const unsigned short* kg = g_kb + head * (NPIX * 8);
    const unsigned short* vg = g_vb + head * (NPIX * 8);

    for (int e = tid; e < 2 * 44 * 60; e += 128) {
        int arr = (e >= 44 * 60) ? 1 : 0;
        int i = e - arr * (44 * 60);
        int r = i / 60, col = i - r * 60;
        int hh = min(max(th0 - 16 + r, 0), 127);
        int ww = min(max(tw0 - 16 + col, 0), 127);
        const unsigned short* src = arr ? vg : kg;
        smu[arr * PL_B + r * HS_B + bswz(col)] =
            *reinterpret_cast<const uint4*>(src + (hh * 128 + ww) * 8);
    }
    __syncthreads();

    const int qy   = tid >> 3;                      // 0..15
    const int qx8  = tid & 7;
    const int wloc = (qx8 & 3) + ((qx8 >> 2) << 4); // 0..3, 16..19
    const int h  = th0 + qy;
    const int wb = tw0 + wloc;                      // quad pixels wb + 4t

    ulonglong2 qA[4], qB[4];
    #pragma unroll
    for (int t = 0; t < 4; t++) {
        const float* qp = &g_q[(head * NPIX + h * 128 + wb + 4 * t) * 8];
        qA[t] = *reinterpret_cast<const ulonglong2*>(qp);
        qB[t] = *reinterpret_cast<const ulonglong2*>(qp + 4);
    }

    float l[4] = {0.f, 0.f, 0.f, 0.f};
    ull acc2[4][4];
    #pragma unroll
    for (int t = 0; t < 4; t++)
        #pragma unroll
        for (int i = 0; i < 4; i++) acc2[t][i] = 0ull;

    #pragma unroll
    for (int a = 0; a < 8; a++) {
        int oh = 4 * a - 16;
        bool vr = (unsigned)(h + oh) < 128u;
        int rbase = (qy + 16 + oh) * HS_B;
        #pragma unroll
        for (int s = 0; s < 11; s++) {
            int off = rbase + bswz(wloc + 4 * s);
            bool ok = vr && ((unsigned)(wb + 4 * s - 16) < 128u);
            uint4 ku = smu[off];
            uint4 vu = smu[PL_B + off];
            ull kp0 = b2u(ku.x), kp1 = b2u(ku.y), kp2 = b2u(ku.z), kp3 = b2u(ku.w);
            ull vp0 = b2u(vu.x), vp1 = b2u(vu.y), vp2 = b2u(vu.z), vp3 = b2u(vu.w);
            #pragma unroll
            for (int t = 0; t < 4; t++) {
                if (t > s || t < s - 7) continue;
                ull s2 = 0ull;
                FMA2(s2, kp0, qA[t].x);
                FMA2(s2, kp1, qA[t].y);
                FMA2(s2, kp2, qB[t].x);
                FMA2(s2, kp3, qB[t].y);
                float2 sf = upk(s2);
                float sc = ok ? (sf.x + sf.y) : -1e30f;
                float ee = __expf(sc);
                l[t] += ee;
                ull e2 = pk(ee, ee);
                FMA2(acc2[t][0], vp0, e2);
                FMA2(acc2[t][1], vp1, e2);
                FMA2(acc2[t][2], vp2, e2);
                FMA2(acc2[t][3], vp3, e2);
            }
        }
    }
    #pragma unroll
    for (int t = 0; t < 4; t++) {
        float rl = 1.0f / l[t];
        int p = h * 128 + wb + 4 * t;
        #pragma unroll
        for (int i = 0; i < 4; i++) {
            float2 f = upk(acc2[t][i]);
            g_att[(head * 8 + 2 * i)     * NPIX + p] = f.x * rl;
            g_att[(head * 8 + 2 * i + 1) * NPIX + p] = f.y * rl;
        }
    }
}

// =================================================================
// Kernel C: proj GEMM + residual + LN2.  256 thr = 16ot(4out) x 16pt(4px)
// =================================================================
static constexpr int SMEM_C = (64 * 68 + 64 * 68) * 4;   // 34816

__global__ void __launch_bounds__(256)
kC(const float* __restrict__ x, const float* __restrict__ projw, const float* __restrict__ projb,
   const float* __restrict__ g1, const float* __restrict__ n2w, const float* __restrict__ n2b)
{
    extern __shared__ float sm[];
    float* as = sm;               // [64][68]
    float* wt = sm + 64 * 68;     // [64][68]
    float* rsum = sm;             // reused: [64][17]
    float* rsq  = sm + 64 * 17;
    float* mv   = sm + 128 * 17;
    float* iv   = sm + 128 * 17 + 64;
    const int tid = threadIdx.x;
    const int ot = tid >> 4, pt = tid & 15;
    const int p0 = blockIdx.x * 64;

    for (int i = tid; i < 64 * 64; i += 256) {
        int o = i >> 6, c = i & 63;
        wt[c * 68 + o] = projw[i];
    }
    for (int i = tid; i < 64 * 64; i += 256) {
        int c = i >> 6, pp = i & 63;
        as[c * 68 + pp] = g_att[c * NPIX + p0 + pp];
    }
    __syncthreads();

    ull acc2[4][2];
    #pragma unroll
    for (int oi = 0; oi < 4; oi++) { acc2[oi][0] = 0ull; acc2[oi][1] = 0ull; }

    #pragma unroll 4
    for (int c = 0; c < 64; c++) {
        float4 w0 = *reinterpret_cast<const float4*>(&wt[c * 68 + ot * 4]);
        ulonglong2 xa = *reinterpret_cast<const ulonglong2*>(&as[c * 68 + pt * 4]);
        float wf[4] = {w0.x, w0.y, w0.z, w0.w};
        #pragma unroll
        for (int oi = 0; oi < 4; oi++) {
            ull wp = pk(wf[oi], wf[oi]);
            FMA2(acc2[oi][0], wp, xa.x);
            FMA2(acc2[oi][1], wp, xa.y);
        }
    }
    __syncthreads();   // done with as/wt

    float x1v[4][4];
    float ps[4] = {0.f,0.f,0.f,0.f}, pq[4] = {0.f,0.f,0.f,0.f};
    #pragma unroll
    for (int oi = 0; oi < 4; oi++) {
        int ch = ot * 4 + oi;
        float pb = projb[ch], gg = g1[ch];
        float4 xr = *reinterpret_cast<const float4*>(&x[ch * NPIX + p0 + pt * 4]);
        float xf[4] = {xr.x, xr.y, xr.z, xr.w};
        #pragma unroll
        for (int pj = 0; pj < 2; pj++) {
            float2 f = upk(acc2[oi][pj]);
            float v0 = xf[2*pj]   + gg * (f.x + pb);
            float v1 = xf[2*pj+1] + gg * (f.y + pb);
            x1v[oi][2*pj] = v0; x1v[oi][2*pj+1] = v1;
            ps[2*pj] += v0;  ps[2*pj+1] += v1;
            pq[2*pj] += v0 * v0; pq[2*pj+1] += v1 * v1;
        }
        float4* d4 = reinterpret_cast<float4*>(&g_x1[ch * NPIX + p0 + pt * 4]);
        *d4 = make_float4(x1v[oi][0], x1v[oi][1], x1v[oi][2], x1v[oi][3]);
    }
    #pragma unroll
    for (int j = 0; j < 4; j++) {
        rsum[(pt * 4 + j) * 17 + ot] = ps[j];
        rsq [(pt * 4 + j) * 17 + ot] = pq[j];
    }
    __syncthreads();
    if (tid < 64) {
        float s = 0.f, q = 0.f;
        #pragma unroll
        for (int k = 0; k < 16; k++) { s += rsum[tid * 17 + k]; q += rsq[tid * 17 + k]; }
        float mean = s * (1.f / 64);
        float var = q * (1.f / 64) - mean * mean;
        mv[tid] = mean;
        iv[tid] = rsqrtf(var + LNEPS);
    }
    __syncthreads();
    float mj[4], ij[4];
    #pragma unroll
    for (int j = 0; j < 4; j++) { mj[j] = mv[pt * 4 + j]; ij[j] = iv[pt * 4 + j]; }
    #pragma unroll
    for (int oi = 0; oi < 4; oi++) {
        int ch = ot * 4 + oi;
        float nw = n2w[ch], nb = n2b[ch];
        float y[4];
        #pragma unroll
        for (int j = 0; j < 4; j++) y[j] = (x1v[oi][j] - mj[j]) * ij[j] * nw + nb;
        float4* d4 = reinterpret_cast<float4*>(&g_y[ch * NPIX + p0 + pt * 4]);
        *d4 = make_float4(y[0], y[1], y[2], y[3]);
    }
}

// =================================================================
// Kernel D: fc1 GEMM + LN + SiLU.  256 thr = 16ot(8out) x 16pt(4px)
// =================================================================
static constexpr int SMEM_D = (64 * 68 + 64 * 132) * 4;   // 51200

__global__ void __launch_bounds__(256)
kD(const float* __restrict__ fc1w, const float* __restrict__ fc1b,
   const float* __restrict__ mnw, const float* __restrict__ mnb)
{
    extern __shared__ float sm[];
    float* ys = sm;               // [64][68]
    float* wt = sm + 64 * 68;     // [64][132]
    float* rsum = sm;             // reused: [64][17]
    float* rsq  = sm + 64 * 17;
    float* mv   = sm + 128 * 17;
    float* iv   = sm + 128 * 17 + 64;
    const int tid = threadIdx.x;
    const int ot = tid >> 4, pt = tid & 15;
    const int p0 = blockIdx.x * 64;

    for (int i = tid; i < 128 * 64; i += 256) {
        int o = i >> 6, c = i & 63;
        wt[c * 132 + o] = fc1w[i];
    }
    for (int i = tid; i < 64 * 64; i += 256) {
        int c = i >> 6, pp = i & 63;
        ys[c * 68 + pp] = g_y[c * NPIX + p0 + pp];
    }
    __syncthreads();

    ull acc2[8][2];
    #pragma unroll
    for (int oi = 0; oi < 8; oi++) { acc2[oi][0] = 0ull; acc2[oi][1] = 0ull; }

    #pragma unroll 4
    for (int c = 0; c < 64; c++) {
        float4 w0 = *reinterpret_cast<const float4*>(&wt[c * 132 + ot * 8]);
        float4 w1 = *reinterpret_cast<const float4*>(&wt[c * 132 + ot * 8 + 4]);
        ulonglong2 xa = *reinterpret_cast<const ulonglong2*>(&ys[c * 68 + pt * 4]);
        float wf[8] = {w0.x, w0.y, w0.z, w0.w, w1.x, w1.y, w1.z, w1.w};
        #pragma unroll
        for (int oi = 0; oi < 8; oi++) {
            ull wp = pk(wf[oi], wf[oi]);
            FMA2(acc2[oi][0], wp, xa.x);
            FMA2(acc2[oi][1], wp, xa.y);
        }
    }
    __syncthreads();

    float hv[8][4];
    float ps[4] = {0.f,0.f,0.f,0.f}, pq[4] = {0.f,0.f,0.f,0.f};
    #pragma unroll
    for (int oi = 0; oi < 8; oi++) {
        float fb = fc1b[ot * 8 + oi];
        #pragma unroll
        for (int pj = 0; pj < 2; pj++) {
            float2 f = upk(acc2[oi][pj]);
            float v0 = f.x + fb, v1 = f.y + fb;
            hv[oi][2*pj] = v0; hv[oi][2*pj+1] = v1;
            ps[2*pj] += v0;  ps[2*pj+1] += v1;
            pq[2*pj] += v0 * v0; pq[2*pj+1] += v1 * v1;
        }
    }
    #pragma unroll
    for (int j = 0; j < 4; j++) {
        rsum[(pt * 4 + j) * 17 + ot] = ps[j];
        rsq [(pt * 4 + j) * 17 + ot] = pq[j];
    }
    __syncthreads();
    if (tid < 64) {
        float s = 0.f, q = 0.f;
        #pragma unroll
        for (int k = 0; k < 16; k++) { s += rsum[tid * 17 + k]; q += rsq[tid * 17 + k]; }
        float mean = s * (1.f / 128);
        float var = q * (1.f / 128) - mean * mean;
        mv[tid] = mean;
        iv[tid] = rsqrtf(var + LNEPS);
    }
    __syncthreads();
    float mj[4], ij[4];
    #pragma unroll
    for (int j = 0; j < 4; j++) { mj[j] = mv[pt * 4 + j]; ij[j] = iv[pt * 4 + j]; }
    #pragma unroll
    for (int oi = 0; oi < 8; oi++) {
        int ch = ot * 8 + oi;
        float nw = mnw[ch], nb = mnb[ch];
        float o4[4];
        #pragma unroll
        for (int j = 0; j < 4; j++) {
            float hh = (hv[oi][j] - mj[j]) * ij[j] * nw + nb;
            o4[j] = hh / (1.f + __expf(-hh));
        }
        float4* d4 = reinterpret_cast<float4*>(&g_h1[ch * NPIX + p0 + pt * 4]);
        *d4 = make_float4(o4[0], o4[1], o4[2], o4[3]);
    }
}

// =================================================================
// Kernel E: fc2 GEMM + residual -> out.  256 thr = 16ot(4out) x 16pt(4px)
// =================================================================
static constexpr int SMEM_E = (128 * 68 + 128 * 68) * 4;   // 69632

__global__ void __launch_bounds__(256)
kE(const float* __restrict__ fc2w, const float* __restrict__ fc2b,
   const float* __restrict__ g2, float* __restrict__ out)
{
    extern __shared__ float sm[];
    float* hs = sm;                // [128][68]
    float* wt = sm + 128 * 68;     // [128][68]
    const int tid = threadIdx.x;
    const int ot = tid >> 4, pt = tid & 15;
    const int p0 = blockIdx.x * 64;

    for (int i = tid; i < 64 * 128; i += 256) {
        int o = i >> 7, c = i & 127;
        wt[c * 68 + o] = fc2w[i];
    }
    for (int i = tid; i < 128 * 64; i += 256) {
        int c = i >> 6, pp = i & 63;
        hs[c * 68 + pp] = g_h1[c * NPIX + p0 + pp];
    }
    __syncthreads();

    ull acc2[4][2];
    #pragma unroll
    for (int oi = 0; oi < 4; oi++) { acc2[oi][0] = 0ull; acc2[oi][1] = 0ull; }

    #pragma unroll 4
    for (int c = 0; c < 128; c++) {
        float4 w0 = *reinterpret_cast<const float4*>(&wt[c * 68 + ot * 4]);
        ulonglong2 xa = *reinterpret_cast<const ulonglong2*>(&hs[c * 68 + pt * 4]);
        float wf[4] = {w0.x, w0.y, w0.z, w0.w};
        #pragma unroll
        for (int oi = 0; oi < 4; oi++) {
            ull wp = pk(wf[oi], wf[oi]);
            FMA2(acc2[oi][0], wp, xa.x);
            FMA2(acc2[oi][1], wp, xa.y);
        }
    }

    #pragma unroll
    for (int oi = 0; oi < 4; oi++) {
        int ch = ot * 4 + oi;
        float fb = fc2b[ch], gg = g2[ch];
        float4 xr = *reinterpret_cast<const float4*>(&g_x1[ch * NPIX + p0 + pt * 4]);
        float xf[4] = {xr.x, xr.y, xr.z, xr.w};
        float o4[4];
        #pragma unroll
        for (int pj = 0; pj < 2; pj++) {
            float2 f = upk(acc2[oi][pj]);
            o4[2*pj]   = xf[2*pj]   + gg * (f.x + fb);
            o4[2*pj+1] = xf[2*pj+1] + gg * (f.y + fb);
        }
        float4* d4 = reinterpret_cast<float4*>(&out[ch * NPIX + p0 + pt * 4]);
        *d4 = make_float4(o4[0], o4[1], o4[2], o4[3]);
    }
}

// =================================================================
extern "C" void kernel_launch(void* const* d_in, const int* in_sizes, int n_in,
                              void* d_out, int out_size)
{
    const float* x     = (const float*)d_in[0];
    const float* n1w   = (const float*)d_in[1];
    const float* n1b   = (const float*)d_in[2];
    const float* qkvw  = (const float*)d_in[3];
    const float* qkvb  = (const float*)d_in[4];
    const float* qnw   = (const float*)d_in[5];
    const float* qnb   = (const float*)d_in[6];
    const float* knw   = (const float*)d_in[7];
    const float* knb   = (const float*)d_in[8];
    const float* projw = (const float*)d_in[9];
    const float* projb = (const float*)d_in[10];
    const float* g1    = (const float*)d_in[11];
    const float* n2w   = (const float*)d_in[12];
    const float* n2b   = (const float*)d_in[13];
    const float* fc1w  = (const float*)d_in[14];
    const float* fc1b  = (const float*)d_in[15];
    const float* mnw   = (const float*)d_in[16];
    const float* mnb   = (const float*)d_in[17];
    const float* fc2w  = (const float*)d_in[18];
    const float* fc2b  = (const float*)d_in[19];
    const float* g2    = (const float*)d_in[20];
    float* out = (float*)d_out;

    cudaFuncSetAttribute(kA, cudaFuncAttributeMaxDynamicSharedMemorySize, SMEM_A);
    cudaFuncSetAttribute(kB, cudaFuncAttributeMaxDynamicSharedMemorySize, SMEM_B);
    cudaFuncSetAttribute(kC, cudaFuncAttributeMaxDynamicSharedMemorySize, SMEM_C);
    cudaFuncSetAttribute(kD, cudaFuncAttributeMaxDynamicSharedMemorySize, SMEM_D);
    cudaFuncSetAttribute(kE, cudaFuncAttributeMaxDynamicSharedMemorySize, SMEM_E);

    kA<<<256, 384, SMEM_A>>>(x, n1w, n1b, qkvw, qkvb, qnw, qnb, knw, knb);
    kB<<<dim3(32, 8), 128, SMEM_B>>>();
    kC<<<256, 256, SMEM_C>>>(x, projw, projb, g1, n2w, n2b);
    kD<<<256, 256, SMEM_D>>>(fc1w, fc1b, mnw, mnb);
    kE<<<256, 256, SMEM_E>>>(fc2w, fc2b, g2, out);
}